// round 1
// baseline (speedup 1.0000x reference)
#include <cuda_runtime.h>

// ---------------------------------------------------------------------------
// Light_PAM on GB300.
// Stage 1: 512 batches [C=256, L=256]   (alpha1 == 0 in this dataset -> exact
//          identity; kernels check alpha1 at runtime and early-exit; a full
//          generic fallback path exists for alpha1 != 0).
// Stage 2: 2048 batches [C=256, L=64], one fused CTA per batch:
//          fb=Wb@x+bb, fc=Wc@x+bc, attn=softmax(fb^T fc),
//          t = x @ attn^T, out = alpha*(Wd@t + bd) + x
//          (uses sum_m attn[l,m] == 1 so bd folds in after the big GEMM).
// All GEMM inner loops use packed fma.rn.f32x2 (FFMA2) — 2x fp32 FMA rate on
// sm_103a vs 3-reg FFMA.
// ---------------------------------------------------------------------------

__device__ float g_out1[8 * 256 * 128 * 128];  // stage-1 output (alpha1 != 0 path only)
__device__ float g_WdT[256 * 256];             // Wd2 transposed [k][c]

__device__ __forceinline__ unsigned long long pack2(float lo, float hi) {
    unsigned long long r;
    asm("mov.b64 %0, {%1, %2};" : "=l"(r) : "f"(lo), "f"(hi));
    return r;
}
__device__ __forceinline__ void fma2(unsigned long long& d, unsigned long long a,
                                     unsigned long long b) {
    asm("fma.rn.f32x2 %0, %1, %2, %0;" : "+l"(d) : "l"(a), "l"(b));
}
__device__ __forceinline__ float2 unpack2(unsigned long long v) {
    float lo, hi;
    asm("mov.b64 {%0, %1}, %2;" : "=f"(lo), "=f"(hi) : "l"(v));
    float2 f; f.x = lo; f.y = hi; return f;
}

// --------------------------------------------------------------------------
// Transpose Wd2 [c][k] -> g_WdT [k][c]  (tiny, 256KB)
// --------------------------------------------------------------------------
__global__ void k_transpose(const float* __restrict__ W) {
    int i = blockIdx.x * 256 + threadIdx.x;  // 65536 total
    int k = i >> 8, c = i & 255;
    g_WdT[i] = W[c * 256 + k];
}

// --------------------------------------------------------------------------
// Generic stage-1 PAM (only executes when alpha1 != 0). Correctness-first.
// Batch b: n = b>>6, p_h = (b&63)>>3, p_w = b&7.  l: q_h = l>>4, q_w = l&15.
// elem addr = n*4194304 + c*16384 + (q_h*8+p_h)*128 + q_w*8 + p_w
// --------------------------------------------------------------------------
__global__ void __launch_bounds__(256) k_stage1(
    const float* __restrict__ x,
    const float* __restrict__ Wb, const float* __restrict__ bb,
    const float* __restrict__ Wc, const float* __restrict__ bc,
    const float* __restrict__ Wd, const float* __restrict__ bd,
    const float* __restrict__ alpha1p)
{
    if (*alpha1p == 0.0f) return;  // exact identity: 0*fe + x == x
    extern __shared__ float sm[];
    float* fbS  = sm;            // 32*256 [o][l]
    float* fcS  = sm + 8192;     // 32*256
    float* rowS = sm + 16384;    // 256
    float* tS   = sm + 16640;    // 256
    float* redS = sm + 16896;    // 8

    int tid = threadIdx.x;
    int b = blockIdx.x;
    int n = b >> 6, p = b & 63;
    int ph = p >> 3, pw = p & 7;
    int base = n * 4194304 + ph * 128 + pw;

    // fb, fc: thread handles column l = tid
    {
        int l = tid;
        int off = ((l >> 4) << 10) + ((l & 15) << 3);
        float ab[32], ac[32];
        #pragma unroll
        for (int o = 0; o < 32; o++) { ab[o] = bb[o]; ac[o] = bc[o]; }
        for (int c = 0; c < 256; c++) {
            float xv = x[base + c * 16384 + off];
            #pragma unroll
            for (int o = 0; o < 32; o++) {
                ab[o] += Wb[o * 256 + c] * xv;
                ac[o] += Wc[o * 256 + c] * xv;
            }
        }
        #pragma unroll
        for (int o = 0; o < 32; o++) { fbS[o * 256 + l] = ab[o]; fcS[o * 256 + l] = ac[o]; }
    }
    __syncthreads();

    float a1 = *alpha1p;
    for (int lr = 0; lr < 256; ++lr) {
        int m = tid;
        float e = 0.f;
        #pragma unroll
        for (int o = 0; o < 32; o++) e += fbS[o * 256 + lr] * fcS[o * 256 + m];
        // block max
        float v = e;
        #pragma unroll
        for (int s = 16; s > 0; s >>= 1) v = fmaxf(v, __shfl_xor_sync(0xffffffffu, v, s));
        if ((tid & 31) == 0) redS[tid >> 5] = v;
        __syncthreads();
        float mx = redS[0];
        #pragma unroll
        for (int w = 1; w < 8; w++) mx = fmaxf(mx, redS[w]);
        float pe = __expf(e - mx);
        v = pe;
        #pragma unroll
        for (int s = 16; s > 0; s >>= 1) v += __shfl_xor_sync(0xffffffffu, v, s);
        __syncthreads();
        if ((tid & 31) == 0) redS[tid >> 5] = v;
        __syncthreads();
        float ssum = 0.f;
        #pragma unroll
        for (int w = 0; w < 8; w++) ssum += redS[w];
        rowS[m] = pe / ssum;
        __syncthreads();
        // t column: thread c
        int c = tid;
        float tv = 0.f;
        for (int mm = 0; mm < 256; mm++)
            tv += x[base + c * 16384 + ((mm >> 4) << 10) + ((mm & 15) << 3)] * rowS[mm];
        tS[c] = tv;
        __syncthreads();
        // fe column + output
        float fv = bd[c];
        for (int k = 0; k < 256; k++) fv += Wd[c * 256 + k] * tS[k];
        int oa = base + c * 16384 + ((lr >> 4) << 10) + ((lr & 15) << 3);
        g_out1[oa] = a1 * fv + x[oa];
        __syncthreads();
    }
}

// --------------------------------------------------------------------------
// Fused stage-2 PAM. One CTA per batch (2048 CTAs, 256 threads).
// Batch b: n = b>>8, q_h = (b&255)>>4, q_w = b&15.  l: p_h = l>>3, p_w = l&7.
// elem addr = n*4194304 + c*16384 + (q_h*8+p_h)*128 + q_w*8 + p_w
// smem (floats):
//   xs   [0,16384)       x tile [c][l], stride 64
//   tbuf [16384,32768)   first WbS(8192)+WcS(8192), then t[k][l] stride 64
//   fbS  [32768,34816)   [o][l] stride 64
//   fcS  [34816,36864)
//   attT [36864,41024)   attn^T [m][l], stride 65 (pad: conflict-free writes)
//   panA [41024,45120)   Wd panel double buffer [kk][c]
//   panB [45120,49216)
// total 49216 floats = 196864 B
// --------------------------------------------------------------------------
__global__ void __launch_bounds__(256, 1) k_stage2(
    const float* __restrict__ x,
    const float* __restrict__ Wb, const float* __restrict__ bb,
    const float* __restrict__ Wc, const float* __restrict__ bc,
    const float* __restrict__ bd,
    const float* __restrict__ alphap, const float* __restrict__ alpha1p,
    float* __restrict__ out)
{
    extern __shared__ float sm[];
    float* xs   = sm;
    float* tbuf = sm + 16384;
    float* fbS  = sm + 32768;
    float* fcS  = sm + 34816;
    float* attT = sm + 36864;
    float* panA = sm + 41024;
    float* panB = sm + 45120;

    int tid = threadIdx.x;
    int b = blockIdx.x;
    int n = b >> 8, q = b & 255;
    int qh = q >> 4, qw = q & 15;
    const float* src = (*alpha1p == 0.0f) ? x : g_out1;
    int base0 = n * 4194304 + qh * 1024 + qw * 8;

    // ---- Phase 1: load x tile + Wb + Wc into smem ----
    {
        float* WbS = tbuf;
        float* WcS = tbuf + 8192;
        const float4* wb4 = (const float4*)Wb;
        const float4* wc4 = (const float4*)Wc;
        float4* wbS4 = (float4*)WbS;
        float4* wcS4 = (float4*)WcS;
        #pragma unroll
        for (int j = 0; j < 8; j++) {
            wbS4[tid + j * 256] = wb4[tid + j * 256];
            wcS4[tid + j * 256] = wc4[tid + j * 256];
        }
        #pragma unroll
        for (int it = 0; it < 8; ++it) {
            int pr = tid + it * 256;      // (c, p_h) pair
            int c = pr >> 3, ph = pr & 7;
            const float4* g = (const float4*)(src + base0 + c * 16384 + ph * 128);
            float4 v0 = g[0], v1 = g[1];
            float* d = xs + c * 64 + ph * 8;
            *(float4*)d = v0;
            *(float4*)(d + 4) = v1;
        }
    }
    __syncthreads();

    // ---- Phase 2: fb = Wb@x + bb, fc = Wc@x + bc  ([32][64]) ----
    {
        float* WbS = tbuf;
        float* WcS = tbuf + 8192;
        int og = tid >> 4;            // 0..15, 2 output rows each
        int l0 = (tid & 15) << 2;     // 0,4,...,60
        int o0 = og * 2;
        unsigned long long ab[2][2], ac[2][2];
        #pragma unroll
        for (int j = 0; j < 2; j++) {
            float bv = bb[o0 + j], cv = bc[o0 + j];
            ab[j][0] = pack2(bv, bv); ab[j][1] = pack2(bv, bv);
            ac[j][0] = pack2(cv, cv); ac[j][1] = pack2(cv, cv);
        }
        for (int c = 0; c < 256; c++) {
            unsigned long long x0 = *(const unsigned long long*)(xs + c * 64 + l0);
            unsigned long long x1 = *(const unsigned long long*)(xs + c * 64 + l0 + 2);
            #pragma unroll
            for (int j = 0; j < 2; j++) {
                float wb = WbS[(o0 + j) * 256 + c];
                float wc = WcS[(o0 + j) * 256 + c];
                unsigned long long wb2 = pack2(wb, wb);
                unsigned long long wc2 = pack2(wc, wc);
                fma2(ab[j][0], wb2, x0); fma2(ab[j][1], wb2, x1);
                fma2(ac[j][0], wc2, x0); fma2(ac[j][1], wc2, x1);
            }
        }
        #pragma unroll
        for (int j = 0; j < 2; j++) {
            *(unsigned long long*)(fbS + (o0 + j) * 64 + l0)     = ab[j][0];
            *(unsigned long long*)(fbS + (o0 + j) * 64 + l0 + 2) = ab[j][1];
            *(unsigned long long*)(fcS + (o0 + j) * 64 + l0)     = ac[j][0];
            *(unsigned long long*)(fcS + (o0 + j) * 64 + l0 + 2) = ac[j][1];
        }
    }
    __syncthreads();

    // ---- Phase 3: E = fb^T fc, row softmax -> attT[m][l] (stride 65) ----
    {
        int warp = tid >> 5, lane = tid & 31;
        for (int r = 0; r < 8; ++r) {
            int l = warp * 8 + r;
            float e0 = 0.f, e1 = 0.f;
            #pragma unroll
            for (int o = 0; o < 32; o++) {
                float fbv = fbS[o * 64 + l];
                e0 += fbv * fcS[o * 64 + lane];
                e1 += fbv * fcS[o * 64 + lane + 32];
            }
            float mx = fmaxf(e0, e1);
            #pragma unroll
            for (int s = 16; s > 0; s >>= 1) mx = fmaxf(mx, __shfl_xor_sync(0xffffffffu, mx, s));
            float p0 = __expf(e0 - mx), p1 = __expf(e1 - mx);
            float ssum = p0 + p1;
            #pragma unroll
            for (int s = 16; s > 0; s >>= 1) ssum += __shfl_xor_sync(0xffffffffu, ssum, s);
            float inv = __fdividef(1.f, ssum);
            attT[lane * 65 + l]        = p0 * inv;
            attT[(lane + 32) * 65 + l] = p1 * inv;
        }
    }
    __syncthreads();

    int ct = tid >> 4, lt = tid & 15;
    int c0 = ct * 16, l0 = lt * 4;

    // ---- Phase 4: t = xs @ attn^T  -> tbuf[k][l] (overwrites WbS/WcS) ----
    {
        unsigned long long acc[16][2];
        #pragma unroll
        for (int i = 0; i < 16; i++) { acc[i][0] = 0ull; acc[i][1] = 0ull; }
        for (int m = 0; m < 64; m++) {
            float b00 = attT[m * 65 + l0],     b01 = attT[m * 65 + l0 + 1];
            float b10 = attT[m * 65 + l0 + 2], b11 = attT[m * 65 + l0 + 3];
            unsigned long long bp0 = pack2(b00, b01);
            unsigned long long bp1 = pack2(b10, b11);
            #pragma unroll
            for (int i = 0; i < 16; i++) {
                float a = xs[(c0 + i) * 64 + m];
                unsigned long long a2 = pack2(a, a);
                fma2(acc[i][0], a2, bp0);
                fma2(acc[i][1], a2, bp1);
            }
        }
        #pragma unroll
        for (int i = 0; i < 16; i++) {
            *(unsigned long long*)(tbuf + (c0 + i) * 64 + l0)     = acc[i][0];
            *(unsigned long long*)(tbuf + (c0 + i) * 64 + l0 + 2) = acc[i][1];
        }
    }
    __syncthreads();

    // ---- Phase 5: fe = WdT-panels @ t, epilogue out = alpha*(fe+bd) + x ----
    {
        unsigned long long acc[16][2];
        #pragma unroll
        for (int i = 0; i < 16; i++) { acc[i][0] = 0ull; acc[i][1] = 0ull; }
        const float4* W4 = (const float4*)g_WdT;  // [k][c], 64 float4 per row
        float4 pre[4];
        #pragma unroll
        for (int j = 0; j < 4; j++) pre[j] = W4[tid + j * 256];  // panel 0
        {
            float4* d4 = (float4*)panA;
            #pragma unroll
            for (int j = 0; j < 4; j++) d4[tid + j * 256] = pre[j];
        }
        __syncthreads();

        for (int p = 0; p < 16; p++) {
            if (p + 1 < 16) {
                #pragma unroll
                for (int j = 0; j < 4; j++) pre[j] = W4[(p + 1) * 1024 + tid + j * 256];
            }
            const float* pan = (p & 1) ? panB : panA;
            int kb = p * 16;
            #pragma unroll
            for (int kk = 0; kk < 16; kk++) {
                unsigned long long bp0 = *(const unsigned long long*)(tbuf + (kb + kk) * 64 + l0);
                unsigned long long bp1 = *(const unsigned long long*)(tbuf + (kb + kk) * 64 + l0 + 2);
                const float* arow = pan + kk * 256 + c0;
                float4 a0 = *(const float4*)(arow);
                float4 a1 = *(const float4*)(arow + 4);
                float4 a2 = *(const float4*)(arow + 8);
                float4 a3 = *(const float4*)(arow + 12);
                float av[16] = {a0.x, a0.y, a0.z, a0.w, a1.x, a1.y, a1.z, a1.w,
                                a2.x, a2.y, a2.z, a2.w, a3.x, a3.y, a3.z, a3.w};
                #pragma unroll
                for (int i = 0; i < 16; i++) {
                    unsigned long long aa = pack2(av[i], av[i]);
                    fma2(acc[i][0], aa, bp0);
                    fma2(acc[i][1], aa, bp1);
                }
            }
            __syncthreads();
            if (p + 1 < 16) {
                float4* d4 = (float4*)((p & 1) ? panA : panB);
                #pragma unroll
                for (int j = 0; j < 4; j++) d4[tid + j * 256] = pre[j];
                __syncthreads();
            }
        }

        float alpha = *alphap;
        int ph0 = l0 >> 3, pw0 = l0 & 7;
        int obase = base0 + ph0 * 128 + pw0;
        #pragma unroll
        for (int i = 0; i < 16; i++) {
            int c = c0 + i;
            float bdv = bd[c];
            float2 f0 = unpack2(acc[i][0]);
            float2 f1 = unpack2(acc[i][1]);
            const float* xr = xs + c * 64 + l0;
            float4 o4;
            o4.x = alpha * (f0.x + bdv) + xr[0];
            o4.y = alpha * (f0.y + bdv) + xr[1];
            o4.z = alpha * (f1.x + bdv) + xr[2];
            o4.w = alpha * (f1.y + bdv) + xr[3];
            *(float4*)(out + obase + c * 16384) = o4;
        }
    }
}

// --------------------------------------------------------------------------
extern "C" void kernel_launch(void* const* d_in, const int* in_sizes, int n_in,
                              void* d_out, int out_size)
{
    (void)in_sizes; (void)n_in; (void)out_size;
    const float* x   = (const float*)d_in[0];
    const float* Wb1 = (const float*)d_in[1];
    const float* bb1 = (const float*)d_in[2];
    const float* Wc1 = (const float*)d_in[3];
    const float* bc1 = (const float*)d_in[4];
    const float* Wd1 = (const float*)d_in[5];
    const float* bd1 = (const float*)d_in[6];
    const float* a1  = (const float*)d_in[7];
    const float* Wb2 = (const float*)d_in[8];
    const float* bb2 = (const float*)d_in[9];
    const float* Wc2 = (const float*)d_in[10];
    const float* bc2 = (const float*)d_in[11];
    const float* Wd2 = (const float*)d_in[12];
    const float* bd2 = (const float*)d_in[13];
    const float* a2  = (const float*)d_in[14];
    float* out = (float*)d_out;

    const int S1SMEM = (8192 + 8192 + 256 + 256 + 8) * 4;
    const int S2SMEM = 49216 * 4;
    cudaFuncSetAttribute(k_stage1, cudaFuncAttributeMaxDynamicSharedMemorySize, S1SMEM);
    cudaFuncSetAttribute(k_stage2, cudaFuncAttributeMaxDynamicSharedMemorySize, S2SMEM);

    k_transpose<<<256, 256>>>(Wd2);
    k_stage1<<<512, 256, S1SMEM>>>(x, Wb1, bb1, Wc1, bc1, Wd1, bd1, a1);
    k_stage2<<<2048, 256, S2SMEM>>>(x, Wb2, bb2, Wc2, bc2, bd2, a2, a1, out);
}

// round 4
// speedup vs baseline: 1.6153x; 1.6153x over previous
#include <cuda_runtime.h>
#include <cuda_bf16.h>
#include <cstdint>

// ---------------------------------------------------------------------------
// Light_PAM on GB300, round 3: hoisted channel GEMM on HMMA (mma.sync bf16).
//   Y  = Wd@x, FB = Wb@x, FC = Wc@x computed in ONE global GEMM:
//   Wcat = [Wd; Wb; Wc; 0] (384x256 bf16)  @  XT (pix x cin bf16).
//   Per-batch attention kernel: E = fb^T fc (fp32), softmax, fe = Y@attnT
//   (FFMA2), epilogue out = alpha*(fe+bd) + x  (bd folds: softmax rows sum 1).
//   alpha1 == 0 in this dataset -> stage-1 identity; generic fp32 fallback
//   (k_stage1 -> g_out1) handles alpha1 != 0.
//   NOTE: tcgen05 is unavailable (harness PTX target is sm_103, not sm_103a);
//   tensor work goes through mma.sync m16n8k16 bf16 (HMMA).
// ---------------------------------------------------------------------------

__device__ float          g_out1[8 * 256 * 128 * 128];     // alpha1!=0 fallback
__device__ __nv_bfloat16  g_XT[8 * 16384 * 256];           // x^T per n: [pixel][cin]
__device__ __nv_bfloat16  g_Ybf[8 * 256 * 16384];          // Y = Wd@x (bf16)
__device__ float          g_FBv[8 * 32 * 16384];           // Wb@x (no bias)
__device__ float          g_FCv[8 * 32 * 16384];           // Wc@x (no bias)
__device__ __nv_bfloat16  g_Wcat[384 * 256];               // [Wd;Wb;Wc;0] bf16

// ---------------- helpers --------------------------------------------------
__device__ __forceinline__ uint32_t smem_u32(const void* p) {
    uint32_t a;
    asm("{ .reg .u64 t; cvta.to.shared.u64 t, %1; cvt.u32.u64 %0, t; }" : "=r"(a) : "l"(p));
    return a;
}
__device__ __forceinline__ unsigned long long pack2(float lo, float hi) {
    unsigned long long r;
    asm("mov.b64 %0, {%1, %2};" : "=l"(r) : "f"(lo), "f"(hi));
    return r;
}
__device__ __forceinline__ void fma2(unsigned long long& d, unsigned long long a,
                                     unsigned long long b) {
    asm("fma.rn.f32x2 %0, %1, %2, %0;" : "+l"(d) : "l"(a), "l"(b));
}
__device__ __forceinline__ float2 unpack2(unsigned long long v) {
    float lo, hi;
    asm("mov.b64 {%0, %1}, %2;" : "=f"(lo), "=f"(hi) : "l"(v));
    float2 f; f.x = lo; f.y = hi; return f;
}
__device__ __forceinline__ uint32_t cvt2bf(float lo, float hi) {
    uint32_t r;
    asm("cvt.rn.bf16x2.f32 %0, %1, %2;" : "=r"(r) : "f"(hi), "f"(lo));
    return r;
}
#define LDSM_X4(r0, r1, r2, r3, addr) \
    asm volatile("ldmatrix.sync.aligned.m8n8.x4.shared.b16 {%0,%1,%2,%3}, [%4];" \
                 : "=r"(r0), "=r"(r1), "=r"(r2), "=r"(r3) : "r"(addr))
#define LDSM_X2(r0, r1, addr) \
    asm volatile("ldmatrix.sync.aligned.m8n8.x2.shared.b16 {%0,%1}, [%2];" \
                 : "=r"(r0), "=r"(r1) : "r"(addr))
__device__ __forceinline__ void mma_bf16(float* c, const uint32_t* a, const uint32_t* b) {
    asm volatile("mma.sync.aligned.m16n8k16.row.col.f32.bf16.bf16.f32 "
                 "{%0,%1,%2,%3}, {%4,%5,%6,%7}, {%8,%9}, {%0,%1,%2,%3};"
                 : "+f"(c[0]), "+f"(c[1]), "+f"(c[2]), "+f"(c[3])
                 : "r"(a[0]), "r"(a[1]), "r"(a[2]), "r"(a[3]), "r"(b[0]), "r"(b[1]));
}

// --------------------------------------------------------------------------
// Prep: Wcat bf16 = [Wd2; Wb2; Wc2; zeros]  (384 x 256)
// --------------------------------------------------------------------------
__global__ void k_prep_w(const float* __restrict__ Wd, const float* __restrict__ Wb,
                         const float* __restrict__ Wc) {
    int row = blockIdx.x, k = threadIdx.x;
    float v = 0.f;
    if (row < 256)      v = Wd[row * 256 + k];
    else if (row < 288) v = Wb[(row - 256) * 256 + k];
    else if (row < 320) v = Wc[(row - 288) * 256 + k];
    g_Wcat[row * 256 + k] = __float2bfloat16(v);
}

// --------------------------------------------------------------------------
// Prep: XT[n][pixel][cin] bf16 (transpose-convert of src[n][cin][pixel]).
// Grid (256, 8), 256 threads. Tile: 64 pixels x 256 cin.
// --------------------------------------------------------------------------
__global__ void __launch_bounds__(256) k_prep_xt(const float* __restrict__ x,
                                                 const float* __restrict__ a1p) {
    __shared__ __nv_bfloat16 sT[64 * 264];  // [pix][cin], pad 8
    const float* src = (*a1p == 0.f) ? x : g_out1;
    int n = blockIdx.y, pix0 = blockIdx.x * 64;
    int tid = threadIdx.x;
    size_t nb = (size_t)n * 4194304;
    #pragma unroll
    for (int it = 0; it < 16; it++) {
        int flat = it * 256 + tid;
        int cin = flat >> 4, jf = flat & 15;
        float4 v = *(const float4*)(src + nb + (size_t)cin * 16384 + pix0 + jf * 4);
        int p = jf * 4;
        sT[(p + 0) * 264 + cin] = __float2bfloat16(v.x);
        sT[(p + 1) * 264 + cin] = __float2bfloat16(v.y);
        sT[(p + 2) * 264 + cin] = __float2bfloat16(v.z);
        sT[(p + 3) * 264 + cin] = __float2bfloat16(v.w);
    }
    __syncthreads();
    #pragma unroll
    for (int it = 0; it < 8; it++) {
        int flat = it * 256 + tid;
        int p = flat >> 5, j = flat & 31;
        uint4 val = *(const uint4*)(sT + p * 264 + j * 8);
        *(uint4*)(g_XT + nb + (size_t)(pix0 + p) * 256 + j * 8) = val;
    }
}

// --------------------------------------------------------------------------
// HMMA GEMM: D[mrow, pix] = sum_k Wcat[mrow,k] * XT[n][pix][k]
// Grid (128 pixel-tiles, 3 m-tiles, 8 n), 256 threads.
// CTA tile M=128, N=128 pixels, K=256 in 4 chunks of 64.
// 8 warps: warp grid 2(m) x 4(n), warp tile 64x32 (4x4 m16n8 mma tiles).
// smem: A[128][72] bf16 + B[128][72] bf16 (pad 72 -> conflict-free ldmatrix).
// m-tiles 0,1 -> Y (bf16); m-tile 2 rows 0-31 -> FB, 32-63 -> FC (fp32).
// --------------------------------------------------------------------------
__global__ void __launch_bounds__(256) k_gemm() {
    __shared__ __nv_bfloat16 sA[128 * 72];
    __shared__ __nv_bfloat16 sB[128 * 72];

    int tid = threadIdx.x, lane = tid & 31, wid = tid >> 5;
    int warp_m = wid >> 2, warp_n = wid & 3;
    int mt = blockIdx.y, n = blockIdx.z;
    int pix0 = blockIdx.x * 128;
    size_t nb = (size_t)n * 4194304;

    const __nv_bfloat16* Arow = g_Wcat + mt * 128 * 256;
    const __nv_bfloat16* Brow = g_XT + nb + (size_t)pix0 * 256;

    float acc[4][4][4];
    #pragma unroll
    for (int mi = 0; mi < 4; mi++)
        #pragma unroll
        for (int ni = 0; ni < 4; ni++)
            #pragma unroll
            for (int j = 0; j < 4; j++) acc[mi][ni][j] = 0.f;

    // ldmatrix per-thread base addresses (bytes); row stride 144B (72 bf16)
    uint32_t aBase = smem_u32(sA) +
        (uint32_t)((warp_m * 64 + (lane & 15)) * 144 + ((lane >> 4) << 4));
    uint32_t bBase = smem_u32(sB) +
        (uint32_t)((warp_n * 32 + (lane & 7)) * 144 + (((lane >> 3) & 1) << 4));

    for (int kc = 0; kc < 4; kc++) {
        // load chunk: 128 rows x 64 bf16 each for A and B (4 uint4/thread each)
        uint4 ra[4], rb[4];
        #pragma unroll
        for (int v = 0; v < 4; v++) {
            int flat = v * 256 + tid;
            int r = flat >> 3, j = flat & 7;
            ra[v] = *(const uint4*)(Arow + r * 256 + kc * 64 + j * 8);
            rb[v] = *(const uint4*)(Brow + (size_t)r * 256 + kc * 64 + j * 8);
        }
        if (kc) __syncthreads();
        #pragma unroll
        for (int v = 0; v < 4; v++) {
            int flat = v * 256 + tid;
            int r = flat >> 3, j = flat & 7;
            *(uint4*)(sA + r * 72 + j * 8) = ra[v];
            *(uint4*)(sB + r * 72 + j * 8) = rb[v];
        }
        __syncthreads();

        #pragma unroll
        for (int ks = 0; ks < 4; ks++) {
            uint32_t af[4][4], bf[4][2];
            #pragma unroll
            for (int mi = 0; mi < 4; mi++)
                LDSM_X4(af[mi][0], af[mi][1], af[mi][2], af[mi][3],
                        aBase + mi * 16 * 144 + ks * 32);
            #pragma unroll
            for (int ni = 0; ni < 4; ni++)
                LDSM_X2(bf[ni][0], bf[ni][1], bBase + ni * 8 * 144 + ks * 32);
            #pragma unroll
            for (int mi = 0; mi < 4; mi++)
                #pragma unroll
                for (int ni = 0; ni < 4; ni++)
                    mma_bf16(acc[mi][ni], af[mi], bf[ni]);
        }
    }

    // ---- epilogue ----
    int mrow_l = warp_m * 64 + (lane >> 2);           // + mi*16 (+8)
    int pcol = pix0 + warp_n * 32 + 2 * (lane & 3);   // + ni*8
    if (mt < 2) {
        #pragma unroll
        for (int mi = 0; mi < 4; mi++) {
            #pragma unroll
            for (int ni = 0; ni < 4; ni++) {
                int c = mt * 128 + mrow_l + mi * 16;
                int p = pcol + ni * 8;
                *(uint32_t*)(g_Ybf + nb + (size_t)c * 16384 + p) =
                    cvt2bf(acc[mi][ni][0], acc[mi][ni][1]);
                *(uint32_t*)(g_Ybf + nb + (size_t)(c + 8) * 16384 + p) =
                    cvt2bf(acc[mi][ni][2], acc[mi][ni][3]);
            }
        }
    } else if (warp_m == 0) {  // rows 0-63 of third block: FB(0-31), FC(32-63)
        #pragma unroll
        for (int mi = 0; mi < 4; mi++) {
            #pragma unroll
            for (int half = 0; half < 2; half++) {
                int r = mrow_l + mi * 16 + half * 8;
                float* dst = (r < 32)
                    ? g_FBv + (size_t)n * 524288 + (size_t)r * 16384
                    : g_FCv + (size_t)n * 524288 + (size_t)(r - 32) * 16384;
                #pragma unroll
                for (int ni = 0; ni < 4; ni++) {
                    float2 v;
                    v.x = acc[mi][ni][half * 2];
                    v.y = acc[mi][ni][half * 2 + 1];
                    *(float2*)(dst + pcol + ni * 8) = v;
                }
            }
        }
    }
}

// --------------------------------------------------------------------------
// Generic stage-1 PAM fallback (alpha1 != 0 only).
// --------------------------------------------------------------------------
__global__ void __launch_bounds__(256) k_stage1(
    const float* __restrict__ x,
    const float* __restrict__ Wb, const float* __restrict__ bb,
    const float* __restrict__ Wc, const float* __restrict__ bc,
    const float* __restrict__ Wd, const float* __restrict__ bd,
    const float* __restrict__ alpha1p)
{
    if (*alpha1p == 0.0f) return;
    extern __shared__ float sm[];
    float* fbS  = sm;
    float* fcS  = sm + 8192;
    float* rowS = sm + 16384;
    float* tS   = sm + 16640;
    float* redS = sm + 16896;

    int tid = threadIdx.x;
    int b = blockIdx.x;
    int n = b >> 6, p = b & 63;
    int ph = p >> 3, pw = p & 7;
    int base = n * 4194304 + ph * 128 + pw;
    {
        int l = tid;
        int off = ((l >> 4) << 10) + ((l & 15) << 3);
        float ab[32], ac[32];
        #pragma unroll
        for (int o = 0; o < 32; o++) { ab[o] = bb[o]; ac[o] = bc[o]; }
        for (int c = 0; c < 256; c++) {
            float xv = x[base + c * 16384 + off];
            #pragma unroll
            for (int o = 0; o < 32; o++) {
                ab[o] += Wb[o * 256 + c] * xv;
                ac[o] += Wc[o * 256 + c] * xv;
            }
        }
        #pragma unroll
        for (int o = 0; o < 32; o++) { fbS[o * 256 + l] = ab[o]; fcS[o * 256 + l] = ac[o]; }
    }
    __syncthreads();
    float a1 = *alpha1p;
    for (int lr = 0; lr < 256; ++lr) {
        int m = tid;
        float e = 0.f;
        #pragma unroll
        for (int o = 0; o < 32; o++) e += fbS[o * 256 + lr] * fcS[o * 256 + m];
        float v = e;
        #pragma unroll
        for (int s = 16; s > 0; s >>= 1) v = fmaxf(v, __shfl_xor_sync(0xffffffffu, v, s));
        if ((tid & 31) == 0) redS[tid >> 5] = v;
        __syncthreads();
        float mx = redS[0];
        #pragma unroll
        for (int w = 1; w < 8; w++) mx = fmaxf(mx, redS[w]);
        float pe = __expf(e - mx);
        v = pe;
        #pragma unroll
        for (int s = 16; s > 0; s >>= 1) v += __shfl_xor_sync(0xffffffffu, v, s);
        __syncthreads();
        if ((tid & 31) == 0) redS[tid >> 5] = v;
        __syncthreads();
        float ssum = 0.f;
        #pragma unroll
        for (int w = 0; w < 8; w++) ssum += redS[w];
        rowS[m] = pe / ssum;
        __syncthreads();
        int c = tid;
        float tv = 0.f;
        for (int mm = 0; mm < 256; mm++)
            tv += x[base + c * 16384 + ((mm >> 4) << 10) + ((mm & 15) << 3)] * rowS[mm];
        tS[c] = tv;
        __syncthreads();
        float fv = bd[c];
        for (int k = 0; k < 256; k++) fv += Wd[c * 256 + k] * tS[k];
        int oa = base + c * 16384 + ((lr >> 4) << 10) + ((lr & 15) << 3);
        g_out1[oa] = a1 * fv + x[oa];
        __syncthreads();
    }
}

// --------------------------------------------------------------------------
// Per-batch attention: E = fb^T fc, softmax, fe = Y@attnT, epilogue.
// 2048 CTAs of 256 threads, ~97KB smem -> 2 CTAs/SM.
// smem (floats): fbS[32*64] | fcS[32*64] | attT[64*66] | Ys[256*65]
// --------------------------------------------------------------------------
__global__ void __launch_bounds__(256, 2) k_attn(
    const float* __restrict__ x,
    const float* __restrict__ bb, const float* __restrict__ bc,
    const float* __restrict__ bd,
    const float* __restrict__ alphap, const float* __restrict__ a1p,
    float* __restrict__ out)
{
    extern __shared__ float sm[];
    float* fbS  = sm;                    // [o][l] stride 64
    float* fcS  = sm + 2048;
    float* attT = sm + 4096;             // [m][l] stride 66
    float* Ys   = sm + 4096 + 64 * 66;   // [c][m] stride 65

    int tid = threadIdx.x;
    int b = blockIdx.x;
    int n = b >> 8, q = b & 255;
    int qh = q >> 4, qw = q & 15;
    size_t nb = (size_t)n * 4194304;
    int pixbase = qh * 1024 + qw * 8;
    const float* src = (*a1p == 0.f) ? x : g_out1;

    // ---- load fb/fc tiles (+bias) ----
    {
        int o = tid >> 3, ph = tid & 7;
        float bbv = bb[o], bcv = bc[o];
        const float* fg = g_FBv + (size_t)n * 524288 + (size_t)o * 16384 + pixbase + ph * 128;
        const float* cg = g_FCv + (size_t)n * 524288 + (size_t)o * 16384 + pixbase + ph * 128;
        float4 b0 = *(const float4*)fg, b1 = *(const float4*)(fg + 4);
        float4 c0 = *(const float4*)cg, c1 = *(const float4*)(cg + 4);
        float* fd = fbS + o * 64 + ph * 8;
        float* cd = fcS + o * 64 + ph * 8;
        fd[0] = b0.x + bbv; fd[1] = b0.y + bbv; fd[2] = b0.z + bbv; fd[3] = b0.w + bbv;
        fd[4] = b1.x + bbv; fd[5] = b1.y + bbv; fd[6] = b1.z + bbv; fd[7] = b1.w + bbv;
        cd[0] = c0.x + bcv; cd[1] = c0.y + bcv; cd[2] = c0.z + bcv; cd[3] = c0.w + bcv;
        cd[4] = c1.x + bcv; cd[5] = c1.y + bcv; cd[6] = c1.z + bcv; cd[7] = c1.w + bcv;
    }
    // ---- load Y tile (bf16 -> fp32 smem) ----
    #pragma unroll
    for (int it = 0; it < 8; it++) {
        int flat = it * 256 + tid;
        int c = flat >> 3, ph = flat & 7;
        const __nv_bfloat16* yp = g_Ybf + nb + (size_t)c * 16384 + pixbase + ph * 128;
        uint4 u = *(const uint4*)yp;
        float2 f0 = __bfloat1622float2(*(__nv_bfloat162*)&u.x);
        float2 f1 = __bfloat1622float2(*(__nv_bfloat162*)&u.y);
        float2 f2 = __bfloat1622float2(*(__nv_bfloat162*)&u.z);
        float2 f3 = __bfloat1622float2(*(__nv_bfloat162*)&u.w);
        float* d = Ys + c * 65 + ph * 8;
        d[0] = f0.x; d[1] = f0.y; d[2] = f1.x; d[3] = f1.y;
        d[4] = f2.x; d[5] = f2.y; d[6] = f3.x; d[7] = f3.y;
    }
    __syncthreads();

    // ---- E + softmax -> attT[m][l] ----
    {
        int warp = tid >> 5, lane = tid & 31;
        for (int r = 0; r < 8; ++r) {
            int l = warp * 8 + r;
            float e0 = 0.f, e1 = 0.f;
            #pragma unroll
            for (int o = 0; o < 32; o++) {
                float fbv = fbS[o * 64 + l];
                e0 += fbv * fcS[o * 64 + lane];
                e1 += fbv * fcS[o * 64 + lane + 32];
            }
            float mx = fmaxf(e0, e1);
            #pragma unroll
            for (int s = 16; s > 0; s >>= 1) mx = fmaxf(mx, __shfl_xor_sync(0xffffffffu, mx, s));
            float p0 = __expf(e0 - mx), p1 = __expf(e1 - mx);
            float ssum = p0 + p1;
            #pragma unroll
            for (int s = 16; s > 0; s >>= 1) ssum += __shfl_xor_sync(0xffffffffu, ssum, s);
            float inv = __fdividef(1.f, ssum);
            attT[lane * 66 + l]        = p0 * inv;
            attT[(lane + 32) * 66 + l] = p1 * inv;
        }
    }
    __syncthreads();

    // ---- fe = Ys @ attnT, epilogue out = alpha*(fe+bd) + src ----
    {
        int ct = tid >> 4, lt = tid & 15;
        int c0 = ct * 16, l0 = lt * 4;
        unsigned long long acc[16][2];
        #pragma unroll
        for (int i = 0; i < 16; i++) { acc[i][0] = 0ull; acc[i][1] = 0ull; }
        for (int m = 0; m < 64; m++) {
            unsigned long long bp0 = *(const unsigned long long*)(attT + m * 66 + l0);
            unsigned long long bp1 = *(const unsigned long long*)(attT + m * 66 + l0 + 2);
            #pragma unroll
            for (int i = 0; i < 16; i++) {
                float a = Ys[(c0 + i) * 65 + m];
                unsigned long long a2 = pack2(a, a);
                fma2(acc[i][0], a2, bp0);
                fma2(acc[i][1], a2, bp1);
            }
        }
        float alpha = *alphap;
        int ph0 = l0 >> 3, pw0 = l0 & 7;
        size_t obase = nb + pixbase + ph0 * 128 + pw0;
        #pragma unroll
        for (int i = 0; i < 16; i++) {
            int c = c0 + i;
            float bdv = bd[c];
            float2 f0 = unpack2(acc[i][0]);
            float2 f1 = unpack2(acc[i][1]);
            float4 xr = *(const float4*)(src + obase + (size_t)c * 16384);
            float4 o4;
            o4.x = alpha * (f0.x + bdv) + xr.x;
            o4.y = alpha * (f0.y + bdv) + xr.y;
            o4.z = alpha * (f1.x + bdv) + xr.z;
            o4.w = alpha * (f1.y + bdv) + xr.w;
            *(float4*)(out + obase + (size_t)c * 16384) = o4;
        }
    }
}

// --------------------------------------------------------------------------
extern "C" void kernel_launch(void* const* d_in, const int* in_sizes, int n_in,
                              void* d_out, int out_size)
{
    (void)in_sizes; (void)n_in; (void)out_size;
    const float* x   = (const float*)d_in[0];
    const float* Wb1 = (const float*)d_in[1];
    const float* bb1 = (const float*)d_in[2];
    const float* Wc1 = (const float*)d_in[3];
    const float* bc1 = (const float*)d_in[4];
    const float* Wd1 = (const float*)d_in[5];
    const float* bd1 = (const float*)d_in[6];
    const float* a1  = (const float*)d_in[7];
    const float* Wb2 = (const float*)d_in[8];
    const float* bb2 = (const float*)d_in[9];
    const float* Wc2 = (const float*)d_in[10];
    const float* bc2 = (const float*)d_in[11];
    const float* Wd2 = (const float*)d_in[12];
    const float* bd2 = (const float*)d_in[13];
    const float* a2  = (const float*)d_in[14];
    float* out = (float*)d_out;

    const int S1SMEM = (8192 + 8192 + 256 + 256 + 8) * 4;
    const int ASMEM  = (4096 + 64 * 66 + 256 * 65) * 4;   // 99840 B
    cudaFuncSetAttribute(k_stage1, cudaFuncAttributeMaxDynamicSharedMemorySize, S1SMEM);
    cudaFuncSetAttribute(k_attn,   cudaFuncAttributeMaxDynamicSharedMemorySize, ASMEM);

    k_prep_w<<<384, 256>>>(Wd2, Wb2, Wc2);
    k_stage1<<<512, 256, S1SMEM>>>(x, Wb1, bb1, Wc1, bc1, Wd1, bd1, a1);
    k_prep_xt<<<dim3(256, 8), 256>>>(x, a1);
    k_gemm<<<dim3(128, 3, 8), 256>>>();
    k_attn<<<2048, 256, ASMEM>>>(x, bb2, bc2, bd2, a2, a1, out);
}

// round 5
// speedup vs baseline: 1.7430x; 1.0790x over previous
#include <cuda_runtime.h>
#include <cuda_bf16.h>
#include <cstdint>

// ---------------------------------------------------------------------------
// Light_PAM on GB300, round 5: HMMA everywhere.
//   Global GEMM (HMMA): Wcat=[Wd;Wb;Wc;0] @ XT -> Y(bf16), FB, FC.
//   Per-batch attention kernel now also HMMA:
//     E = fbT x fc (m16n8k16 bf16, K=32) -> fp32 smem
//     softmax (scalar, 16 vals/thread, quad shuffles) -> attn bf16 [l][m]
//     fe = Ys[c][m] x attn[l][m] (M=256,N=64,K=64) -> epilogue
//   out = alpha*(fe+bd) + x  (bd folds since softmax rows sum to 1).
//   alpha1==0 in dataset -> stage-1 exact identity; generic fp32 fallback
//   (k_stage1 -> g_out1) covers alpha1 != 0.
// ---------------------------------------------------------------------------

__device__ float          g_out1[8 * 256 * 128 * 128];     // alpha1!=0 fallback
__device__ __nv_bfloat16  g_XT[8 * 16384 * 256];           // x^T per n: [pixel][cin]
__device__ __nv_bfloat16  g_Ybf[8 * 256 * 16384];          // Y = Wd@x (bf16)
__device__ float          g_FBv[8 * 32 * 16384];           // Wb@x (no bias)
__device__ float          g_FCv[8 * 32 * 16384];           // Wc@x (no bias)
__device__ __nv_bfloat16  g_Wcat[384 * 256];               // [Wd;Wb;Wc;0] bf16

// ---------------- helpers --------------------------------------------------
__device__ __forceinline__ uint32_t smem_u32(const void* p) {
    uint32_t a;
    asm("{ .reg .u64 t; cvta.to.shared.u64 t, %1; cvt.u32.u64 %0, t; }" : "=r"(a) : "l"(p));
    return a;
}
__device__ __forceinline__ uint32_t cvt2bf(float lo, float hi) {
    uint32_t r;
    asm("cvt.rn.bf16x2.f32 %0, %1, %2;" : "=r"(r) : "f"(hi), "f"(lo));
    return r;
}
#define LDSM_X4(r0, r1, r2, r3, addr) \
    asm volatile("ldmatrix.sync.aligned.m8n8.x4.shared.b16 {%0,%1,%2,%3}, [%4];" \
                 : "=r"(r0), "=r"(r1), "=r"(r2), "=r"(r3) : "r"(addr))
#define LDSM_X2(r0, r1, addr) \
    asm volatile("ldmatrix.sync.aligned.m8n8.x2.shared.b16 {%0,%1}, [%2];" \
                 : "=r"(r0), "=r"(r1) : "r"(addr))
__device__ __forceinline__ void mma_bf16(float* c, const uint32_t* a, const uint32_t* b) {
    asm volatile("mma.sync.aligned.m16n8k16.row.col.f32.bf16.bf16.f32 "
                 "{%0,%1,%2,%3}, {%4,%5,%6,%7}, {%8,%9}, {%0,%1,%2,%3};"
                 : "+f"(c[0]), "+f"(c[1]), "+f"(c[2]), "+f"(c[3])
                 : "r"(a[0]), "r"(a[1]), "r"(a[2]), "r"(a[3]), "r"(b[0]), "r"(b[1]));
}

// --------------------------------------------------------------------------
// Prep: Wcat bf16 = [Wd2; Wb2; Wc2; zeros]  (384 x 256)
// --------------------------------------------------------------------------
__global__ void k_prep_w(const float* __restrict__ Wd, const float* __restrict__ Wb,
                         const float* __restrict__ Wc) {
    int row = blockIdx.x, k = threadIdx.x;
    float v = 0.f;
    if (row < 256)      v = Wd[row * 256 + k];
    else if (row < 288) v = Wb[(row - 256) * 256 + k];
    else if (row < 320) v = Wc[(row - 288) * 256 + k];
    g_Wcat[row * 256 + k] = __float2bfloat16(v);
}

// --------------------------------------------------------------------------
// Prep: XT[n][pixel][cin] bf16 (transpose-convert of src[n][cin][pixel]).
// --------------------------------------------------------------------------
__global__ void __launch_bounds__(256) k_prep_xt(const float* __restrict__ x,
                                                 const float* __restrict__ a1p) {
    __shared__ __nv_bfloat16 sT[64 * 264];
    const float* src = (*a1p == 0.f) ? x : g_out1;
    int n = blockIdx.y, pix0 = blockIdx.x * 64;
    int tid = threadIdx.x;
    size_t nb = (size_t)n * 4194304;
    #pragma unroll
    for (int it = 0; it < 16; it++) {
        int flat = it * 256 + tid;
        int cin = flat >> 4, jf = flat & 15;
        float4 v = *(const float4*)(src + nb + (size_t)cin * 16384 + pix0 + jf * 4);
        int p = jf * 4;
        sT[(p + 0) * 264 + cin] = __float2bfloat16(v.x);
        sT[(p + 1) * 264 + cin] = __float2bfloat16(v.y);
        sT[(p + 2) * 264 + cin] = __float2bfloat16(v.z);
        sT[(p + 3) * 264 + cin] = __float2bfloat16(v.w);
    }
    __syncthreads();
    #pragma unroll
    for (int it = 0; it < 8; it++) {
        int flat = it * 256 + tid;
        int p = flat >> 5, j = flat & 31;
        uint4 val = *(const uint4*)(sT + p * 264 + j * 8);
        *(uint4*)(g_XT + nb + (size_t)(pix0 + p) * 256 + j * 8) = val;
    }
}

// --------------------------------------------------------------------------
// HMMA GEMM: D[mrow, pix] = sum_k Wcat[mrow,k] * XT[n][pix][k]
// Grid (128 pixel-tiles, 3 m-tiles, 8 n), 256 threads, 2 CTAs/SM.
// --------------------------------------------------------------------------
__global__ void __launch_bounds__(256, 2) k_gemm() {
    __shared__ __nv_bfloat16 sA[128 * 72];
    __shared__ __nv_bfloat16 sB[128 * 72];

    int tid = threadIdx.x, lane = tid & 31, wid = tid >> 5;
    int warp_m = wid >> 2, warp_n = wid & 3;
    int mt = blockIdx.y, n = blockIdx.z;
    int pix0 = blockIdx.x * 128;
    size_t nb = (size_t)n * 4194304;

    const __nv_bfloat16* Arow = g_Wcat + mt * 128 * 256;
    const __nv_bfloat16* Brow = g_XT + nb + (size_t)pix0 * 256;

    float acc[4][4][4];
    #pragma unroll
    for (int mi = 0; mi < 4; mi++)
        #pragma unroll
        for (int ni = 0; ni < 4; ni++)
            #pragma unroll
            for (int j = 0; j < 4; j++) acc[mi][ni][j] = 0.f;

    uint32_t aBase = smem_u32(sA) +
        (uint32_t)((warp_m * 64 + (lane & 15)) * 144 + ((lane >> 4) << 4));
    uint32_t bBase = smem_u32(sB) +
        (uint32_t)((warp_n * 32 + (lane & 7)) * 144 + (((lane >> 3) & 1) << 4));

    for (int kc = 0; kc < 4; kc++) {
        uint4 ra[4], rb[4];
        #pragma unroll
        for (int v = 0; v < 4; v++) {
            int flat = v * 256 + tid;
            int r = flat >> 3, j = flat & 7;
            ra[v] = *(const uint4*)(Arow + r * 256 + kc * 64 + j * 8);
            rb[v] = *(const uint4*)(Brow + (size_t)r * 256 + kc * 64 + j * 8);
        }
        if (kc) __syncthreads();
        #pragma unroll
        for (int v = 0; v < 4; v++) {
            int flat = v * 256 + tid;
            int r = flat >> 3, j = flat & 7;
            *(uint4*)(sA + r * 72 + j * 8) = ra[v];
            *(uint4*)(sB + r * 72 + j * 8) = rb[v];
        }
        __syncthreads();

        #pragma unroll
        for (int ks = 0; ks < 4; ks++) {
            uint32_t af[4][4], bf[4][2];
            #pragma unroll
            for (int mi = 0; mi < 4; mi++)
                LDSM_X4(af[mi][0], af[mi][1], af[mi][2], af[mi][3],
                        aBase + mi * 16 * 144 + ks * 32);
            #pragma unroll
            for (int ni = 0; ni < 4; ni++)
                LDSM_X2(bf[ni][0], bf[ni][1], bBase + ni * 8 * 144 + ks * 32);
            #pragma unroll
            for (int mi = 0; mi < 4; mi++)
                #pragma unroll
                for (int ni = 0; ni < 4; ni++)
                    mma_bf16(acc[mi][ni], af[mi], bf[ni]);
        }
    }

    int mrow_l = warp_m * 64 + (lane >> 2);
    int pcol = pix0 + warp_n * 32 + 2 * (lane & 3);
    if (mt < 2) {
        #pragma unroll
        for (int mi = 0; mi < 4; mi++) {
            #pragma unroll
            for (int ni = 0; ni < 4; ni++) {
                int c = mt * 128 + mrow_l + mi * 16;
                int p = pcol + ni * 8;
                *(uint32_t*)(g_Ybf + nb + (size_t)c * 16384 + p) =
                    cvt2bf(acc[mi][ni][0], acc[mi][ni][1]);
                *(uint32_t*)(g_Ybf + nb + (size_t)(c + 8) * 16384 + p) =
                    cvt2bf(acc[mi][ni][2], acc[mi][ni][3]);
            }
        }
    } else if (warp_m == 0) {
        #pragma unroll
        for (int mi = 0; mi < 4; mi++) {
            #pragma unroll
            for (int half = 0; half < 2; half++) {
                int r = mrow_l + mi * 16 + half * 8;
                float* dst = (r < 32)
                    ? g_FBv + (size_t)n * 524288 + (size_t)r * 16384
                    : g_FCv + (size_t)n * 524288 + (size_t)(r - 32) * 16384;
                #pragma unroll
                for (int ni = 0; ni < 4; ni++) {
                    float2 v;
                    v.x = acc[mi][ni][half * 2];
                    v.y = acc[mi][ni][half * 2 + 1];
                    *(float2*)(dst + pcol + ni * 8) = v;
                }
            }
        }
    }
}

// --------------------------------------------------------------------------
// Generic stage-1 PAM fallback (alpha1 != 0 only).
// --------------------------------------------------------------------------
__global__ void __launch_bounds__(256) k_stage1(
    const float* __restrict__ x,
    const float* __restrict__ Wb, const float* __restrict__ bb,
    const float* __restrict__ Wc, const float* __restrict__ bc,
    const float* __restrict__ Wd, const float* __restrict__ bd,
    const float* __restrict__ alpha1p)
{
    if (*alpha1p == 0.0f) return;
    extern __shared__ float sm[];
    float* fbS  = sm;
    float* fcS  = sm + 8192;
    float* rowS = sm + 16384;
    float* tS   = sm + 16640;
    float* redS = sm + 16896;

    int tid = threadIdx.x;
    int b = blockIdx.x;
    int n = b >> 6, p = b & 63;
    int ph = p >> 3, pw = p & 7;
    int base = n * 4194304 + ph * 128 + pw;
    {
        int l = tid;
        int off = ((l >> 4) << 10) + ((l & 15) << 3);
        float ab[32], ac[32];
        #pragma unroll
        for (int o = 0; o < 32; o++) { ab[o] = bb[o]; ac[o] = bc[o]; }
        for (int c = 0; c < 256; c++) {
            float xv = x[base + c * 16384 + off];
            #pragma unroll
            for (int o = 0; o < 32; o++) {
                ab[o] += Wb[o * 256 + c] * xv;
                ac[o] += Wc[o * 256 + c] * xv;
            }
        }
        #pragma unroll
        for (int o = 0; o < 32; o++) { fbS[o * 256 + l] = ab[o]; fcS[o * 256 + l] = ac[o]; }
    }
    __syncthreads();
    float a1 = *alpha1p;
    for (int lr = 0; lr < 256; ++lr) {
        int m = tid;
        float e = 0.f;
        #pragma unroll
        for (int o = 0; o < 32; o++) e += fbS[o * 256 + lr] * fcS[o * 256 + m];
        float v = e;
        #pragma unroll
        for (int s = 16; s > 0; s >>= 1) v = fmaxf(v, __shfl_xor_sync(0xffffffffu, v, s));
        if ((tid & 31) == 0) redS[tid >> 5] = v;
        __syncthreads();
        float mx = redS[0];
        #pragma unroll
        for (int w = 1; w < 8; w++) mx = fmaxf(mx, redS[w]);
        float pe = __expf(e - mx);
        v = pe;
        #pragma unroll
        for (int s = 16; s > 0; s >>= 1) v += __shfl_xor_sync(0xffffffffu, v, s);
        __syncthreads();
        if ((tid & 31) == 0) redS[tid >> 5] = v;
        __syncthreads();
        float ssum = 0.f;
        #pragma unroll
        for (int w = 0; w < 8; w++) ssum += redS[w];
        rowS[m] = pe / ssum;
        __syncthreads();
        int c = tid;
        float tv = 0.f;
        for (int mm = 0; mm < 256; mm++)
            tv += x[base + c * 16384 + ((mm >> 4) << 10) + ((mm & 15) << 3)] * rowS[mm];
        tS[c] = tv;
        __syncthreads();
        float fv = bd[c];
        for (int k = 0; k < 256; k++) fv += Wd[c * 256 + k] * tS[k];
        int oa = base + c * 16384 + ((lr >> 4) << 10) + ((lr & 15) << 3);
        g_out1[oa] = a1 * fv + x[oa];
        __syncthreads();
    }
}

// --------------------------------------------------------------------------
// Per-batch attention, HMMA. 2048 CTAs x 256 threads, 2 CTAs/SM.
// smem (bytes):
//   Ys  [0,36864)         bf16 [256 c][72]  (Y tile, m-contig)
//   fbT [36864,41984)     bf16 [64 l][40]   (fb^T + bias)
//   fcT [41984,47104)     bf16 [64 m][40]   (fc^T + bias)
//   atn [47104,56320)     bf16 [64 l][72]   (softmax rows, m-contig)
//   Es  [56320,73216)     f32  [64 l][66]   (logits)
// --------------------------------------------------------------------------
__global__ void __launch_bounds__(256, 2) k_attn(
    const float* __restrict__ x,
    const float* __restrict__ bb, const float* __restrict__ bc,
    const float* __restrict__ bd,
    const float* __restrict__ alphap, const float* __restrict__ a1p,
    float* __restrict__ out)
{
    extern __shared__ char smb[];
    __nv_bfloat16* Ys  = (__nv_bfloat16*)(smb);
    __nv_bfloat16* fbT = (__nv_bfloat16*)(smb + 36864);
    __nv_bfloat16* fcT = (__nv_bfloat16*)(smb + 41984);
    __nv_bfloat16* atn = (__nv_bfloat16*)(smb + 47104);
    float*         Es  = (float*)(smb + 56320);

    int tid = threadIdx.x, lane = tid & 31, wid = tid >> 5;
    int b = blockIdx.x;
    int n = b >> 8, q = b & 255;
    int qh = q >> 4, qw = q & 15;
    size_t nb = (size_t)n * 4194304;
    int pixbase = qh * 1024 + qw * 8;
    const float* src = (*a1p == 0.f) ? x : g_out1;

    // ---- load Y tile: [c][m] bf16, m = ph*8+pw ----
    #pragma unroll
    for (int it = 0; it < 8; it++) {
        int flat = it * 256 + tid;
        int c = flat >> 3, ph = flat & 7;
        uint4 u = *(const uint4*)(g_Ybf + nb + (size_t)c * 16384 + pixbase + ph * 128);
        *(uint4*)(Ys + c * 72 + ph * 8) = u;
    }
    // ---- load fb/fc, add bias, transpose to bf16 [pix][o] ----
    {
        int o = tid >> 3, ph = tid & 7;
        float bbv = bb[o], bcv = bc[o];
        const float* fg = g_FBv + (size_t)n * 524288 + (size_t)o * 16384 + pixbase + ph * 128;
        const float* cg = g_FCv + (size_t)n * 524288 + (size_t)o * 16384 + pixbase + ph * 128;
        float4 f0 = *(const float4*)fg, f1 = *(const float4*)(fg + 4);
        float4 c0 = *(const float4*)cg, c1 = *(const float4*)(cg + 4);
        int l0 = ph * 8;
        fbT[(l0 + 0) * 40 + o] = __float2bfloat16(f0.x + bbv);
        fbT[(l0 + 1) * 40 + o] = __float2bfloat16(f0.y + bbv);
        fbT[(l0 + 2) * 40 + o] = __float2bfloat16(f0.z + bbv);
        fbT[(l0 + 3) * 40 + o] = __float2bfloat16(f0.w + bbv);
        fbT[(l0 + 4) * 40 + o] = __float2bfloat16(f1.x + bbv);
        fbT[(l0 + 5) * 40 + o] = __float2bfloat16(f1.y + bbv);
        fbT[(l0 + 6) * 40 + o] = __float2bfloat16(f1.z + bbv);
        fbT[(l0 + 7) * 40 + o] = __float2bfloat16(f1.w + bbv);
        fcT[(l0 + 0) * 40 + o] = __float2bfloat16(c0.x + bcv);
        fcT[(l0 + 1) * 40 + o] = __float2bfloat16(c0.y + bcv);
        fcT[(l0 + 2) * 40 + o] = __float2bfloat16(c0.z + bcv);
        fcT[(l0 + 3) * 40 + o] = __float2bfloat16(c0.w + bcv);
        fcT[(l0 + 4) * 40 + o] = __float2bfloat16(c1.x + bcv);
        fcT[(l0 + 5) * 40 + o] = __float2bfloat16(c1.y + bcv);
        fcT[(l0 + 6) * 40 + o] = __float2bfloat16(c1.z + bcv);
        fcT[(l0 + 7) * 40 + o] = __float2bfloat16(c1.w + bcv);
    }
    __syncthreads();

    // ---- E[l][m] = fbT x fcT (K=32): warp grid 4(l) x 2(m) ----
    {
        int lw = wid >> 1, mw = wid & 1;
        uint32_t aBase = smem_u32(fbT) +
            (uint32_t)((lw * 16 + (lane & 15)) * 80 + ((lane >> 4) << 4));
        uint32_t bBase = smem_u32(fcT) +
            (uint32_t)((mw * 32 + (lane & 7)) * 80 + (((lane >> 3) & 1) << 4));
        float e[4][4];
        #pragma unroll
        for (int ni = 0; ni < 4; ni++)
            #pragma unroll
            for (int j = 0; j < 4; j++) e[ni][j] = 0.f;
        #pragma unroll
        for (int ks = 0; ks < 2; ks++) {
            uint32_t a[4];
            LDSM_X4(a[0], a[1], a[2], a[3], aBase + ks * 32);
            #pragma unroll
            for (int ni = 0; ni < 4; ni++) {
                uint32_t bf2[2];
                LDSM_X2(bf2[0], bf2[1], bBase + ni * 8 * 80 + ks * 32);
                mma_bf16(e[ni], a, bf2);
            }
        }
        int row = lw * 16 + (lane >> 2);
        int col = mw * 32 + 2 * (lane & 3);
        #pragma unroll
        for (int ni = 0; ni < 4; ni++) {
            *(float2*)(Es + row * 66 + col + ni * 8) = make_float2(e[ni][0], e[ni][1]);
            *(float2*)(Es + (row + 8) * 66 + col + ni * 8) = make_float2(e[ni][2], e[ni][3]);
        }
    }
    __syncthreads();

    // ---- softmax per row (4 threads/row, 16 vals each) -> atn bf16 ----
    {
        int row = tid >> 2, seg = tid & 3;
        const float* er = Es + row * 66 + seg * 16;
        float v[16];
        #pragma unroll
        for (int i = 0; i < 16; i++) v[i] = er[i];
        float mx = v[0];
        #pragma unroll
        for (int i = 1; i < 16; i++) mx = fmaxf(mx, v[i]);
        mx = fmaxf(mx, __shfl_xor_sync(0xffffffffu, mx, 1));
        mx = fmaxf(mx, __shfl_xor_sync(0xffffffffu, mx, 2));
        float s = 0.f;
        #pragma unroll
        for (int i = 0; i < 16; i++) { v[i] = __expf(v[i] - mx); s += v[i]; }
        s += __shfl_xor_sync(0xffffffffu, s, 1);
        s += __shfl_xor_sync(0xffffffffu, s, 2);
        float inv = __fdividef(1.f, s);
        uint32_t* aw = (uint32_t*)(atn + row * 72 + seg * 16);
        #pragma unroll
        for (int i = 0; i < 8; i++)
            aw[i] = cvt2bf(v[2 * i] * inv, v[2 * i + 1] * inv);
    }
    __syncthreads();

    // ---- fe[c][l] = Ys[c][m] x atn[l][m] (K=64): warp grid 4(c) x 2(l) ----
    {
        int cw = wid >> 1, lw2 = wid & 1;
        uint32_t aBase = smem_u32(Ys) +
            (uint32_t)((cw * 64 + (lane & 15)) * 144 + ((lane >> 4) << 4));
        uint32_t bBase = smem_u32(atn) +
            (uint32_t)((lw2 * 32 + (lane & 7)) * 144 + (((lane >> 3) & 1) << 4));
        float acc[4][4][4];
        #pragma unroll
        for (int mi = 0; mi < 4; mi++)
            #pragma unroll
            for (int ni = 0; ni < 4; ni++)
                #pragma unroll
                for (int j = 0; j < 4; j++) acc[mi][ni][j] = 0.f;
        #pragma unroll
        for (int ks = 0; ks < 4; ks++) {
            uint32_t af[4][4], bf2[4][2];
            #pragma unroll
            for (int mi = 0; mi < 4; mi++)
                LDSM_X4(af[mi][0], af[mi][1], af[mi][2], af[mi][3],
                        aBase + mi * 16 * 144 + ks * 32);
            #pragma unroll
            for (int ni = 0; ni < 4; ni++)
                LDSM_X2(bf2[ni][0], bf2[ni][1], bBase + ni * 8 * 144 + ks * 32);
            #pragma unroll
            for (int mi = 0; mi < 4; mi++)
                #pragma unroll
                for (int ni = 0; ni < 4; ni++)
                    mma_bf16(acc[mi][ni], af[mi], bf2[ni]);
        }

        float alpha = *alphap;
        int crow = cw * 64 + (lane >> 2);
        int lcol = lw2 * 32 + 2 * (lane & 3);
        #pragma unroll
        for (int mi = 0; mi < 4; mi++) {
            #pragma unroll
            for (int half = 0; half < 2; half++) {
                int c = crow + mi * 16 + half * 8;
                float bdv = bd[c];
                size_t rowb = nb + pixbase + (size_t)c * 16384;
                #pragma unroll
                for (int ni = 0; ni < 4; ni++) {
                    int l = lcol + ni * 8;
                    int po = ((l >> 3) << 7) + (l & 7);
                    float2 xr = *(const float2*)(src + rowb + po);
                    float f0 = acc[mi][ni][half * 2];
                    float f1 = acc[mi][ni][half * 2 + 1];
                    float2 o2;
                    o2.x = alpha * (f0 + bdv) + xr.x;
                    o2.y = alpha * (f1 + bdv) + xr.y;
                    *(float2*)(out + rowb + po) = o2;
                }
            }
        }
    }
}

// --------------------------------------------------------------------------
extern "C" void kernel_launch(void* const* d_in, const int* in_sizes, int n_in,
                              void* d_out, int out_size)
{
    (void)in_sizes; (void)n_in; (void)out_size;
    const float* x   = (const float*)d_in[0];
    const float* Wb1 = (const float*)d_in[1];
    const float* bb1 = (const float*)d_in[2];
    const float* Wc1 = (const float*)d_in[3];
    const float* bc1 = (const float*)d_in[4];
    const float* Wd1 = (const float*)d_in[5];
    const float* bd1 = (const float*)d_in[6];
    const float* a1  = (const float*)d_in[7];
    const float* Wb2 = (const float*)d_in[8];
    const float* bb2 = (const float*)d_in[9];
    const float* Wc2 = (const float*)d_in[10];
    const float* bc2 = (const float*)d_in[11];
    const float* Wd2 = (const float*)d_in[12];
    const float* bd2 = (const float*)d_in[13];
    const float* a2  = (const float*)d_in[14];
    float* out = (float*)d_out;

    const int S1SMEM = (8192 + 8192 + 256 + 256 + 8) * 4;
    const int ASMEM  = 73216;
    cudaFuncSetAttribute(k_stage1, cudaFuncAttributeMaxDynamicSharedMemorySize, S1SMEM);
    cudaFuncSetAttribute(k_attn,   cudaFuncAttributeMaxDynamicSharedMemorySize, ASMEM);

    k_prep_w<<<384, 256>>>(Wd2, Wb2, Wc2);
    k_stage1<<<512, 256, S1SMEM>>>(x, Wb1, bb1, Wc1, bc1, Wd1, bd1, a1);
    k_prep_xt<<<dim3(256, 8), 256>>>(x, a1);
    k_gemm<<<dim3(128, 3, 8), 256>>>();
    k_attn<<<2048, 256, ASMEM>>>(x, bb2, bc2, bd2, a2, a1, out);
}

// round 6
// speedup vs baseline: 2.5667x; 1.4726x over previous
#include <cuda_runtime.h>
#include <cuda_bf16.h>
#include <cstdint>

// ---------------------------------------------------------------------------
// Light_PAM on GB300, round 6: HMMA everywhere + cp.async double-buffered
// global GEMM.
//   Global GEMM (HMMA): Wcat=[Wd;Wb;Wc;0] @ XT -> Y(bf16), FB, FC.
//   Per-batch attention kernel (HMMA): E = fbT x fc, softmax, fe = Ys x atn.
//   out = alpha*(fe+bd) + x  (bd folds since softmax rows sum to 1).
//   alpha1==0 in dataset -> stage-1 exact identity; generic fp32 fallback
//   (k_stage1 -> g_out1) covers alpha1 != 0.
// ---------------------------------------------------------------------------

__device__ float          g_out1[8 * 256 * 128 * 128];     // alpha1!=0 fallback
__device__ __nv_bfloat16  g_XT[8 * 16384 * 256];           // x^T per n: [pixel][cin]
__device__ __nv_bfloat16  g_Ybf[8 * 256 * 16384];          // Y = Wd@x (bf16)
__device__ float          g_FBv[8 * 32 * 16384];           // Wb@x (no bias)
__device__ float          g_FCv[8 * 32 * 16384];           // Wc@x (no bias)
__device__ __nv_bfloat16  g_Wcat[384 * 256];               // [Wd;Wb;Wc;0] bf16

// ---------------- helpers --------------------------------------------------
__device__ __forceinline__ uint32_t smem_u32(const void* p) {
    uint32_t a;
    asm("{ .reg .u64 t; cvta.to.shared.u64 t, %1; cvt.u32.u64 %0, t; }" : "=r"(a) : "l"(p));
    return a;
}
__device__ __forceinline__ uint32_t cvt2bf(float lo, float hi) {
    uint32_t r;
    asm("cvt.rn.bf16x2.f32 %0, %1, %2;" : "=r"(r) : "f"(hi), "f"(lo));
    return r;
}
__device__ __forceinline__ void cp16(uint32_t s, const void* g) {
    asm volatile("cp.async.cg.shared.global [%0], [%1], 16;" :: "r"(s), "l"(g));
}
#define CP_COMMIT() asm volatile("cp.async.commit_group;" ::: "memory")
#define CP_WAIT(n)  asm volatile("cp.async.wait_group %0;" :: "n"(n) : "memory")
#define LDSM_X4(r0, r1, r2, r3, addr) \
    asm volatile("ldmatrix.sync.aligned.m8n8.x4.shared.b16 {%0,%1,%2,%3}, [%4];" \
                 : "=r"(r0), "=r"(r1), "=r"(r2), "=r"(r3) : "r"(addr))
#define LDSM_X2(r0, r1, addr) \
    asm volatile("ldmatrix.sync.aligned.m8n8.x2.shared.b16 {%0,%1}, [%2];" \
                 : "=r"(r0), "=r"(r1) : "r"(addr))
__device__ __forceinline__ void mma_bf16(float* c, const uint32_t* a, const uint32_t* b) {
    asm volatile("mma.sync.aligned.m16n8k16.row.col.f32.bf16.bf16.f32 "
                 "{%0,%1,%2,%3}, {%4,%5,%6,%7}, {%8,%9}, {%0,%1,%2,%3};"
                 : "+f"(c[0]), "+f"(c[1]), "+f"(c[2]), "+f"(c[3])
                 : "r"(a[0]), "r"(a[1]), "r"(a[2]), "r"(a[3]), "r"(b[0]), "r"(b[1]));
}

// --------------------------------------------------------------------------
// Prep: Wcat bf16 = [Wd2; Wb2; Wc2; zeros]  (384 x 256)
// --------------------------------------------------------------------------
__global__ void k_prep_w(const float* __restrict__ Wd, const float* __restrict__ Wb,
                         const float* __restrict__ Wc) {
    int row = blockIdx.x, k = threadIdx.x;
    float v = 0.f;
    if (row < 256)      v = Wd[row * 256 + k];
    else if (row < 288) v = Wb[(row - 256) * 256 + k];
    else if (row < 320) v = Wc[(row - 288) * 256 + k];
    g_Wcat[row * 256 + k] = __float2bfloat16(v);
}

// --------------------------------------------------------------------------
// Prep: XT[n][pixel][cin] bf16 (transpose-convert of src[n][cin][pixel]).
// --------------------------------------------------------------------------
__global__ void __launch_bounds__(256) k_prep_xt(const float* __restrict__ x,
                                                 const float* __restrict__ a1p) {
    __shared__ __nv_bfloat16 sT[64 * 264];
    const float* src = (*a1p == 0.f) ? x : g_out1;
    int n = blockIdx.y, pix0 = blockIdx.x * 64;
    int tid = threadIdx.x;
    size_t nb = (size_t)n * 4194304;
    #pragma unroll
    for (int it = 0; it < 16; it++) {
        int flat = it * 256 + tid;
        int cin = flat >> 4, jf = flat & 15;
        float4 v = *(const float4*)(src + nb + (size_t)cin * 16384 + pix0 + jf * 4);
        int p = jf * 4;
        sT[(p + 0) * 264 + cin] = __float2bfloat16(v.x);
        sT[(p + 1) * 264 + cin] = __float2bfloat16(v.y);
        sT[(p + 2) * 264 + cin] = __float2bfloat16(v.z);
        sT[(p + 3) * 264 + cin] = __float2bfloat16(v.w);
    }
    __syncthreads();
    #pragma unroll
    for (int it = 0; it < 8; it++) {
        int flat = it * 256 + tid;
        int p = flat >> 5, j = flat & 31;
        uint4 val = *(const uint4*)(sT + p * 264 + j * 8);
        *(uint4*)(g_XT + nb + (size_t)(pix0 + p) * 256 + j * 8) = val;
    }
}

// --------------------------------------------------------------------------
// HMMA GEMM: D[mrow, pix] = sum_k Wcat[mrow,k] * XT[n][pix][k]
// Grid (128 pixel-tiles, 3 m-tiles, 8 n), 256 threads, 2 CTAs/SM.
// Double-buffered cp.async K-chunks (K=256 in 4 chunks of 64).
// smem per buffer: A[128][72] bf16 (18432B) + B[128][72] bf16 (18432B).
// --------------------------------------------------------------------------
__global__ void __launch_bounds__(256) k_gemm() {
    extern __shared__ char smg[];   // 2 * 36864 bytes
    const int BUFB = 36864;         // bytes per buffer (A + B)
    const int BOFF = 18432;         // B offset inside a buffer

    int tid = threadIdx.x, lane = tid & 31, wid = tid >> 5;
    int warp_m = wid >> 2, warp_n = wid & 3;
    int mt = blockIdx.y, n = blockIdx.z;
    int pix0 = blockIdx.x * 128;
    size_t nb = (size_t)n * 4194304;

    const __nv_bfloat16* Arow = g_Wcat + mt * 128 * 256;
    const __nv_bfloat16* Brow = g_XT + nb + (size_t)pix0 * 256;

    uint32_t sbase = smem_u32(smg);
    int r = tid >> 1, j4 = (tid & 1) << 2;    // A: 128 rows, 2 threads/row (2x16B)
    int smA = r * 144 + j4 * 4;               // byte offset within buffer
    // B: 128 rows x 64 bf16, 256 threads -> each thread 2 rows? use same split:
    // 4 x 16B per thread via flat loop.

    // issue loads for chunk kc into buffer sel
    auto issue = [&](int kc, int sel) {
        uint32_t base = sbase + sel * BUFB;
        #pragma unroll
        for (int v = 0; v < 4; v++) {
            int flat = v * 256 + tid;
            int rr = flat >> 3, jj = flat & 7;
            cp16(base + rr * 144 + jj * 16, Arow + rr * 256 + kc * 64 + jj * 8);
        }
        #pragma unroll
        for (int v = 0; v < 4; v++) {
            int flat = v * 256 + tid;
            int rr = flat >> 3, jj = flat & 7;
            cp16(base + BOFF + rr * 144 + jj * 16,
                 Brow + (size_t)rr * 256 + kc * 64 + jj * 8);
        }
        CP_COMMIT();
    };

    float acc[4][4][4];
    #pragma unroll
    for (int mi = 0; mi < 4; mi++)
        #pragma unroll
        for (int ni = 0; ni < 4; ni++)
            #pragma unroll
            for (int j = 0; j < 4; j++) acc[mi][ni][j] = 0.f;

    uint32_t aOff = (uint32_t)((warp_m * 64 + (lane & 15)) * 144 + ((lane >> 4) << 4));
    uint32_t bOff = (uint32_t)(BOFF + (warp_n * 32 + (lane & 7)) * 144 +
                               (((lane >> 3) & 1) << 4));

    issue(0, 0);
    for (int kc = 0; kc < 4; kc++) {
        if (kc < 3) issue(kc + 1, (kc + 1) & 1);
        if (kc < 3) { CP_WAIT(1); } else { CP_WAIT(0); }
        __syncthreads();

        uint32_t aBase = sbase + (kc & 1) * BUFB + aOff;
        uint32_t bBase = sbase + (kc & 1) * BUFB + bOff;
        #pragma unroll
        for (int ks = 0; ks < 4; ks++) {
            uint32_t af[4][4], bf[4][2];
            #pragma unroll
            for (int mi = 0; mi < 4; mi++)
                LDSM_X4(af[mi][0], af[mi][1], af[mi][2], af[mi][3],
                        aBase + mi * 16 * 144 + ks * 32);
            #pragma unroll
            for (int ni = 0; ni < 4; ni++)
                LDSM_X2(bf[ni][0], bf[ni][1], bBase + ni * 8 * 144 + ks * 32);
            #pragma unroll
            for (int mi = 0; mi < 4; mi++)
                #pragma unroll
                for (int ni = 0; ni < 4; ni++)
                    mma_bf16(acc[mi][ni], af[mi], bf[ni]);
        }
        __syncthreads();
    }

    int mrow_l = warp_m * 64 + (lane >> 2);
    int pcol = pix0 + warp_n * 32 + 2 * (lane & 3);
    if (mt < 2) {
        #pragma unroll
        for (int mi = 0; mi < 4; mi++) {
            #pragma unroll
            for (int ni = 0; ni < 4; ni++) {
                int c = mt * 128 + mrow_l + mi * 16;
                int p = pcol + ni * 8;
                *(uint32_t*)(g_Ybf + nb + (size_t)c * 16384 + p) =
                    cvt2bf(acc[mi][ni][0], acc[mi][ni][1]);
                *(uint32_t*)(g_Ybf + nb + (size_t)(c + 8) * 16384 + p) =
                    cvt2bf(acc[mi][ni][2], acc[mi][ni][3]);
            }
        }
    } else if (warp_m == 0) {
        #pragma unroll
        for (int mi = 0; mi < 4; mi++) {
            #pragma unroll
            for (int half = 0; half < 2; half++) {
                int rr = mrow_l + mi * 16 + half * 8;
                float* dst = (rr < 32)
                    ? g_FBv + (size_t)n * 524288 + (size_t)rr * 16384
                    : g_FCv + (size_t)n * 524288 + (size_t)(rr - 32) * 16384;
                #pragma unroll
                for (int ni = 0; ni < 4; ni++) {
                    float2 v;
                    v.x = acc[mi][ni][half * 2];
                    v.y = acc[mi][ni][half * 2 + 1];
                    *(float2*)(dst + pcol + ni * 8) = v;
                }
            }
        }
    }
    (void)smA; (void)r; (void)j4;
}

// --------------------------------------------------------------------------
// Generic stage-1 PAM fallback (alpha1 != 0 only).
// --------------------------------------------------------------------------
__global__ void __launch_bounds__(256) k_stage1(
    const float* __restrict__ x,
    const float* __restrict__ Wb, const float* __restrict__ bb,
    const float* __restrict__ Wc, const float* __restrict__ bc,
    const float* __restrict__ Wd, const float* __restrict__ bd,
    const float* __restrict__ alpha1p)
{
    if (*alpha1p == 0.0f) return;
    extern __shared__ float sm[];
    float* fbS  = sm;
    float* fcS  = sm + 8192;
    float* rowS = sm + 16384;
    float* tS   = sm + 16640;
    float* redS = sm + 16896;

    int tid = threadIdx.x;
    int b = blockIdx.x;
    int n = b >> 6, p = b & 63;
    int ph = p >> 3, pw = p & 7;
    int base = n * 4194304 + ph * 128 + pw;
    {
        int l = tid;
        int off = ((l >> 4) << 10) + ((l & 15) << 3);
        float ab[32], ac[32];
        #pragma unroll
        for (int o = 0; o < 32; o++) { ab[o] = bb[o]; ac[o] = bc[o]; }
        for (int c = 0; c < 256; c++) {
            float xv = x[base + c * 16384 + off];
            #pragma unroll
            for (int o = 0; o < 32; o++) {
                ab[o] += Wb[o * 256 + c] * xv;
                ac[o] += Wc[o * 256 + c] * xv;
            }
        }
        #pragma unroll
        for (int o = 0; o < 32; o++) { fbS[o * 256 + l] = ab[o]; fcS[o * 256 + l] = ac[o]; }
    }
    __syncthreads();
    float a1 = *alpha1p;
    for (int lr = 0; lr < 256; ++lr) {
        int m = tid;
        float e = 0.f;
        #pragma unroll
        for (int o = 0; o < 32; o++) e += fbS[o * 256 + lr] * fcS[o * 256 + m];
        float v = e;
        #pragma unroll
        for (int s = 16; s > 0; s >>= 1) v = fmaxf(v, __shfl_xor_sync(0xffffffffu, v, s));
        if ((tid & 31) == 0) redS[tid >> 5] = v;
        __syncthreads();
        float mx = redS[0];
        #pragma unroll
        for (int w = 1; w < 8; w++) mx = fmaxf(mx, redS[w]);
        float pe = __expf(e - mx);
        v = pe;
        #pragma unroll
        for (int s = 16; s > 0; s >>= 1) v += __shfl_xor_sync(0xffffffffu, v, s);
        __syncthreads();
        if ((tid & 31) == 0) redS[tid >> 5] = v;
        __syncthreads();
        float ssum = 0.f;
        #pragma unroll
        for (int w = 0; w < 8; w++) ssum += redS[w];
        rowS[m] = pe / ssum;
        __syncthreads();
        int c = tid;
        float tv = 0.f;
        for (int mm = 0; mm < 256; mm++)
            tv += x[base + c * 16384 + ((mm >> 4) << 10) + ((mm & 15) << 3)] * rowS[mm];
        tS[c] = tv;
        __syncthreads();
        float fv = bd[c];
        for (int k = 0; k < 256; k++) fv += Wd[c * 256 + k] * tS[k];
        int oa = base + c * 16384 + ((lr >> 4) << 10) + ((lr & 15) << 3);
        g_out1[oa] = a1 * fv + x[oa];
        __syncthreads();
    }
}

// --------------------------------------------------------------------------
// Per-batch attention, HMMA. 2048 CTAs x 256 threads, 2 CTAs/SM.
// smem (bytes):
//   Ys  [0,36864)         bf16 [256 c][72]  (Y tile, m-contig)
//   fbT [36864,41984)     bf16 [64 l][40]   (fb^T + bias)
//   fcT [41984,47104)     bf16 [64 m][40]   (fc^T + bias)
//   atn [47104,56320)     bf16 [64 l][72]   (softmax rows, m-contig)
//   Es  [56320,73216)     f32  [64 l][66]   (logits)
// --------------------------------------------------------------------------
__global__ void __launch_bounds__(256, 2) k_attn(
    const float* __restrict__ x,
    const float* __restrict__ bb, const float* __restrict__ bc,
    const float* __restrict__ bd,
    const float* __restrict__ alphap, const float* __restrict__ a1p,
    float* __restrict__ out)
{
    extern __shared__ char smb[];
    __nv_bfloat16* Ys  = (__nv_bfloat16*)(smb);
    __nv_bfloat16* fbT = (__nv_bfloat16*)(smb + 36864);
    __nv_bfloat16* fcT = (__nv_bfloat16*)(smb + 41984);
    __nv_bfloat16* atn = (__nv_bfloat16*)(smb + 47104);
    float*         Es  = (float*)(smb + 56320);

    int tid = threadIdx.x, lane = tid & 31, wid = tid >> 5;
    int b = blockIdx.x;
    int n = b >> 8, q = b & 255;
    int qh = q >> 4, qw = q & 15;
    size_t nb = (size_t)n * 4194304;
    int pixbase = qh * 1024 + qw * 8;
    const float* src = (*a1p == 0.f) ? x : g_out1;

    // ---- load Y tile: [c][m] bf16, m = ph*8+pw ----
    #pragma unroll
    for (int it = 0; it < 8; it++) {
        int flat = it * 256 + tid;
        int c = flat >> 3, ph = flat & 7;
        uint4 u = *(const uint4*)(g_Ybf + nb + (size_t)c * 16384 + pixbase + ph * 128);
        *(uint4*)(Ys + c * 72 + ph * 8) = u;
    }
    // ---- load fb/fc, add bias, transpose to bf16 [pix][o] ----
    {
        int o = tid >> 3, ph = tid & 7;
        float bbv = bb[o], bcv = bc[o];
        const float* fg = g_FBv + (size_t)n * 524288 + (size_t)o * 16384 + pixbase + ph * 128;
        const float* cg = g_FCv + (size_t)n * 524288 + (size_t)o * 16384 + pixbase + ph * 128;
        float4 f0 = *(const float4*)fg, f1 = *(const float4*)(fg + 4);
        float4 c0 = *(const float4*)cg, c1 = *(const float4*)(cg + 4);
        int l0 = ph * 8;
        fbT[(l0 + 0) * 40 + o] = __float2bfloat16(f0.x + bbv);
        fbT[(l0 + 1) * 40 + o] = __float2bfloat16(f0.y + bbv);
        fbT[(l0 + 2) * 40 + o] = __float2bfloat16(f0.z + bbv);
        fbT[(l0 + 3) * 40 + o] = __float2bfloat16(f0.w + bbv);
        fbT[(l0 + 4) * 40 + o] = __float2bfloat16(f1.x + bbv);
        fbT[(l0 + 5) * 40 + o] = __float2bfloat16(f1.y + bbv);
        fbT[(l0 + 6) * 40 + o] = __float2bfloat16(f1.z + bbv);
        fbT[(l0 + 7) * 40 + o] = __float2bfloat16(f1.w + bbv);
        fcT[(l0 + 0) * 40 + o] = __float2bfloat16(c0.x + bcv);
        fcT[(l0 + 1) * 40 + o] = __float2bfloat16(c0.y + bcv);
        fcT[(l0 + 2) * 40 + o] = __float2bfloat16(c0.z + bcv);
        fcT[(l0 + 3) * 40 + o] = __float2bfloat16(c0.w + bcv);
        fcT[(l0 + 4) * 40 + o] = __float2bfloat16(c1.x + bcv);
        fcT[(l0 + 5) * 40 + o] = __float2bfloat16(c1.y + bcv);
        fcT[(l0 + 6) * 40 + o] = __float2bfloat16(c1.z + bcv);
        fcT[(l0 + 7) * 40 + o] = __float2bfloat16(c1.w + bcv);
    }
    __syncthreads();

    // ---- E[l][m] = fbT x fcT (K=32): warp grid 4(l) x 2(m) ----
    {
        int lw = wid >> 1, mw = wid & 1;
        uint32_t aBase = smem_u32(fbT) +
            (uint32_t)((lw * 16 + (lane & 15)) * 80 + ((lane >> 4) << 4));
        uint32_t bBase = smem_u32(fcT) +
            (uint32_t)((mw * 32 + (lane & 7)) * 80 + (((lane >> 3) & 1) << 4));
        float e[4][4];
        #pragma unroll
        for (int ni = 0; ni < 4; ni++)
            #pragma unroll
            for (int j = 0; j < 4; j++) e[ni][j] = 0.f;
        #pragma unroll
        for (int ks = 0; ks < 2; ks++) {
            uint32_t a[4];
            LDSM_X4(a[0], a[1], a[2], a[3], aBase + ks * 32);
            #pragma unroll
            for (int ni = 0; ni < 4; ni++) {
                uint32_t bf2[2];
                LDSM_X2(bf2[0], bf2[1], bBase + ni * 8 * 80 + ks * 32);
                mma_bf16(e[ni], a, bf2);
            }
        }
        int row = lw * 16 + (lane >> 2);
        int col = mw * 32 + 2 * (lane & 3);
        #pragma unroll
        for (int ni = 0; ni < 4; ni++) {
            *(float2*)(Es + row * 66 + col + ni * 8) = make_float2(e[ni][0], e[ni][1]);
            *(float2*)(Es + (row + 8) * 66 + col + ni * 8) = make_float2(e[ni][2], e[ni][3]);
        }
    }
    __syncthreads();

    // ---- softmax per row (4 threads/row, 16 vals each) -> atn bf16 ----
    {
        int row = tid >> 2, seg = tid & 3;
        const float* er = Es + row * 66 + seg * 16;
        float v[16];
        #pragma unroll
        for (int i = 0; i < 16; i++) v[i] = er[i];
        float mx = v[0];
        #pragma unroll
        for (int i = 1; i < 16; i++) mx = fmaxf(mx, v[i]);
        mx = fmaxf(mx, __shfl_xor_sync(0xffffffffu, mx, 1));
        mx = fmaxf(mx, __shfl_xor_sync(0xffffffffu, mx, 2));
        float s = 0.f;
        #pragma unroll
        for (int i = 0; i < 16; i++) { v[i] = __expf(v[i] - mx); s += v[i]; }
        s += __shfl_xor_sync(0xffffffffu, s, 1);
        s += __shfl_xor_sync(0xffffffffu, s, 2);
        float inv = __fdividef(1.f, s);
        uint32_t* aw = (uint32_t*)(atn + row * 72 + seg * 16);
        #pragma unroll
        for (int i = 0; i < 8; i++)
            aw[i] = cvt2bf(v[2 * i] * inv, v[2 * i + 1] * inv);
    }
    __syncthreads();

    // ---- fe[c][l] = Ys[c][m] x atn[l][m] (K=64): warp grid 4(c) x 2(l) ----
    {
        int cw = wid >> 1, lw2 = wid & 1;
        uint32_t aBase = smem_u32(Ys) +
            (uint32_t)((cw * 64 + (lane & 15)) * 144 + ((lane >> 4) << 4));
        uint32_t bBase = smem_u32(atn) +
            (uint32_t)((lw2 * 32 + (lane & 7)) * 144 + (((lane >> 3) & 1) << 4));
        float acc[4][4][4];
        #pragma unroll
        for (int mi = 0; mi < 4; mi++)
            #pragma unroll
            for (int ni = 0; ni < 4; ni++)
                #pragma unroll
                for (int j = 0; j < 4; j++) acc[mi][ni][j] = 0.f;
        #pragma unroll
        for (int ks = 0; ks < 4; ks++) {
            uint32_t af[4][4], bf2[4][2];
            #pragma unroll
            for (int mi = 0; mi < 4; mi++)
                LDSM_X4(af[mi][0], af[mi][1], af[mi][2], af[mi][3],
                        aBase + mi * 16 * 144 + ks * 32);
            #pragma unroll
            for (int ni = 0; ni < 4; ni++)
                LDSM_X2(bf2[ni][0], bf2[ni][1], bBase + ni * 8 * 144 + ks * 32);
            #pragma unroll
            for (int mi = 0; mi < 4; mi++)
                #pragma unroll
                for (int ni = 0; ni < 4; ni++)
                    mma_bf16(acc[mi][ni], af[mi], bf2[ni]);
        }

        float alpha = *alphap;
        int crow = cw * 64 + (lane >> 2);
        int lcol = lw2 * 32 + 2 * (lane & 3);
        #pragma unroll
        for (int mi = 0; mi < 4; mi++) {
            #pragma unroll
            for (int half = 0; half < 2; half++) {
                int c = crow + mi * 16 + half * 8;
                float bdv = bd[c];
                size_t rowb = nb + pixbase + (size_t)c * 16384;
                #pragma unroll
                for (int ni = 0; ni < 4; ni++) {
                    int l = lcol + ni * 8;
                    int po = ((l >> 3) << 7) + (l & 7);
                    float2 xr = *(const float2*)(src + rowb + po);
                    float f0 = acc[mi][ni][half * 2];
                    float f1 = acc[mi][ni][half * 2 + 1];
                    float2 o2;
                    o2.x = alpha * (f0 + bdv) + xr.x;
                    o2.y = alpha * (f1 + bdv) + xr.y;
                    *(float2*)(out + rowb + po) = o2;
                }
            }
        }
    }
}

// --------------------------------------------------------------------------
extern "C" void kernel_launch(void* const* d_in, const int* in_sizes, int n_in,
                              void* d_out, int out_size)
{
    (void)in_sizes; (void)n_in; (void)out_size;
    const float* x   = (const float*)d_in[0];
    const float* Wb1 = (const float*)d_in[1];
    const float* bb1 = (const float*)d_in[2];
    const float* Wc1 = (const float*)d_in[3];
    const float* bc1 = (const float*)d_in[4];
    const float* Wd1 = (const float*)d_in[5];
    const float* bd1 = (const float*)d_in[6];
    const float* a1  = (const float*)d_in[7];
    const float* Wb2 = (const float*)d_in[8];
    const float* bb2 = (const float*)d_in[9];
    const float* Wc2 = (const float*)d_in[10];
    const float* bc2 = (const float*)d_in[11];
    const float* Wd2 = (const float*)d_in[12];
    const float* bd2 = (const float*)d_in[13];
    const float* a2  = (const float*)d_in[14];
    float* out = (float*)d_out;

    const int S1SMEM = (8192 + 8192 + 256 + 256 + 8) * 4;
    const int GSMEM  = 2 * 36864;   // 73728 B, 2 CTAs/SM
    const int ASMEM  = 73216;
    cudaFuncSetAttribute(k_stage1, cudaFuncAttributeMaxDynamicSharedMemorySize, S1SMEM);
    cudaFuncSetAttribute(k_gemm,   cudaFuncAttributeMaxDynamicSharedMemorySize, GSMEM);
    cudaFuncSetAttribute(k_attn,   cudaFuncAttributeMaxDynamicSharedMemorySize, ASMEM);

    k_prep_w<<<384, 256>>>(Wd2, Wb2, Wc2);
    k_stage1<<<512, 256, S1SMEM>>>(x, Wb1, bb1, Wc1, bc1, Wd1, bd1, a1);
    k_prep_xt<<<dim3(256, 8), 256>>>(x, a1);
    k_gemm<<<dim3(128, 3, 8), 256, GSMEM>>>();
    k_attn<<<2048, 256, ASMEM>>>(x, bb2, bc2, bd2, a2, a1, out);
}